// round 8
// baseline (speedup 1.0000x reference)
#include <cuda_runtime.h>
#include <cuda_bf16.h>
#include <cstdint>

#define BB 512
#define LL 512
#define NN 128
#define PITCH 136
#define ROWB (PITCH * 2)
#define BUFB (16 * ROWB)
#define GRB 2           // real batches per group
#define NGRP 2          // groups per block

__device__ float g_norm[BB];
__device__ float g_path[BB];

__device__ __forceinline__ uint32_t smem_u32(const void* p) {
    uint32_t a;
    asm("{ .reg .u64 t; cvta.to.shared.u64 t, %1; cvt.u32.u64 %0, t; }"
        : "=r"(a) : "l"(p));
    return a;
}
__device__ __forceinline__ uint32_t bfpack(float lo, float hi) {
    uint32_t d;
    asm("cvt.rn.bf16x2.f32 %0, %1, %2;" : "=r"(d) : "f"(hi), "f"(lo));
    return d;
}
__device__ __forceinline__ float frcp(float x) {
    float r;
    asm("rcp.approx.f32 %0, %1;" : "=f"(r) : "f"(x));
    return r;
}
__device__ __forceinline__ void gbar(int g) {
    asm volatile("bar.sync %0, %1;" :: "r"(g + 1), "r"(128) : "memory");
}
__device__ __forceinline__ void ldm4(uint32_t& a0, uint32_t& a1,
                                     uint32_t& a2, uint32_t& a3, uint32_t addr) {
    asm volatile("ldmatrix.sync.aligned.m8n8.x4.shared.b16 {%0,%1,%2,%3}, [%4];"
                 : "=r"(a0), "=r"(a1), "=r"(a2), "=r"(a3) : "r"(addr));
}
__device__ __forceinline__ void mma16816(float* d,
                                         uint32_t a0, uint32_t a1, uint32_t a2, uint32_t a3,
                                         uint32_t b0, uint32_t b1) {
    asm volatile("mma.sync.aligned.m16n8k16.row.col.f32.bf16.bf16.f32 "
                 "{%0,%1,%2,%3},{%4,%5,%6,%7},{%8,%9},{%0,%1,%2,%3};"
                 : "+f"(d[0]), "+f"(d[1]), "+f"(d[2]), "+f"(d[3])
                 : "r"(a0), "r"(a1), "r"(a2), "r"(a3), "r"(b0), "r"(b1));
}

// ---------------------------------------------------------------------------
// Forward: 128 blocks x 256 threads = 2 independent groups of 128 threads.
// Group = 2 real batches (rows 0-1 of a 16-row MMA tile, rows 2-15 pad 0).
// Warp w of a group owns cols [32w, 32w+32) = 4 n-tiles; E frags resident.
// Linear-domain recurrence; one named barrier per group per step.
// ---------------------------------------------------------------------------
__global__ __launch_bounds__(256, 1)
void crf_forward(const float* __restrict__ em,
                 const float* __restrict__ mask,
                 const float* __restrict__ start,
                 const float* __restrict__ trans) {
    __shared__ __align__(16) __nv_bfloat16 psh[NGRP][2][16 * PITCH];
    __shared__ float rinv[NGRP][2][GRB];
    __shared__ float csh[NGRP][GRB];
    __shared__ float Lsh[NGRP][GRB];
    __shared__ float sred[NGRP][GRB][NN];

    const int tid  = threadIdx.x;
    const int g    = tid >> 7;           // group 0/1
    const int ltid = tid & 127;
    const int w    = ltid >> 5;          // warp 0..3 -> cols [32w, 32w+32)
    const int lane = ltid & 31;
    const int r    = lane >> 2;          // tile row
    const int c2   = lane & 3;
    const bool real = (r < GRB);
    const int b0   = blockIdx.x * (NGRP * GRB) + g * GRB;
    const int b    = b0 + (real ? r : 0);

    // column bases for the 4 n-tiles this thread touches
    int jn[4];
#pragma unroll
    for (int nt = 0; nt < 4; nt++) jn[nt] = 32 * w + 8 * nt + 2 * c2;

    // ---- B fragments: E = exp(trans), 4 n-tiles x 8 k-blocks ----
    uint32_t Bf0[4][8], Bf1[4][8];
    {
        const int kb = 2 * (lane & 3);
#pragma unroll
        for (int nt = 0; nt < 4; nt++) {
            const int jB = 32 * w + 8 * nt + (lane >> 2);
#pragma unroll
            for (int kk = 0; kk < 8; kk++) {
                int k0 = 16 * kk + kb;
                Bf0[nt][kk] = bfpack(__expf(trans[(k0)     * NN + jB]),
                                     __expf(trans[(k0 + 1) * NN + jB]));
                Bf1[nt][kk] = bfpack(__expf(trans[(k0 + 8) * NN + jB]),
                                     __expf(trans[(k0 + 9) * NN + jB]));
            }
        }
    }

    // ---- zero this group's two p buffers (pad rows stay 0 forever) ----
    for (int i = ltid; i < 2 * 16 * PITCH / 2; i += 128)
        ((uint32_t*)psh[g])[i] = 0u;

    const uint32_t psb = smem_u32(&psh[g][0][0]);
    const bool writer = (w == 0 && c2 == 0 && real);

    // ---- init: s0 = start + em0; shift c = s0[col 0] ----
    float2 qv[4];     // this thread's q values (row r), 4 n-tiles x 2 cols
    float  Lr = 0.f;  // register-resident log-offset (writer threads only)
    {
        float2 e0[4];
#pragma unroll
        for (int nt = 0; nt < 4; nt++)
            e0[nt] = real ? *(const float2*)&em[((size_t)b * LL) * NN + jn[nt]]
                          : make_float2(0.f, 0.f);
        float s00 = start[jn[0]] + e0[0].x;
        if (writer) { csh[g][r] = s00; }
        gbar(g);
        float c0 = csh[g][real ? r : 0];
        Lr = c0;
#pragma unroll
        for (int nt = 0; nt < 4; nt++) {
            float sx = start[jn[nt]] + e0[nt].x;
            float sy = start[jn[nt] + 1] + e0[nt].y;
            qv[nt].x = __expf(sx - c0);
            qv[nt].y = __expf(sy - c0);
        }
        if (real) {
#pragma unroll
            for (int nt = 0; nt < 4; nt++)
                *(uint32_t*)((char*)psh[g] + BUFB + r * ROWB + jn[nt] * 2)
                    = bfpack(qv[nt].x, qv[nt].y);
            if (writer) rinv[g][1][r] = frcp(qv[0].x);
        }
    }

    // ---- prefetch t=1 ----
    float2 emv[4];
    float mk = 1.0f;
#pragma unroll
    for (int nt = 0; nt < 4; nt++) emv[nt] = make_float2(0.f, 0.f);
    if (real) {
#pragma unroll
        for (int nt = 0; nt < 4; nt++)
            emv[nt] = *(const float2*)&em[((size_t)b * LL + 1) * NN + jn[nt]];
        mk = mask[b * LL + 1];
    }
    gbar(g);

    for (int t = 1; t < LL; t++) {
        const int pr = t & 1, pw = pr ^ 1;

        // ---- hoisted: inv + combined scales (exp(em) * inv), before MMA ----
        float inv = rinv[g][pr][real ? r : 0];
        float2 sc[4];
#pragma unroll
        for (int nt = 0; nt < 4; nt++) {
            sc[nt].x = __expf(emv[nt].x) * inv;
            sc[nt].y = __expf(emv[nt].y) * inv;
        }

        // ---- prefetch t+1 ----
        float2 env[4];
        float mkn = 1.0f;
#pragma unroll
        for (int nt = 0; nt < 4; nt++) env[nt] = make_float2(0.f, 0.f);
        if (real && t + 1 < LL) {
#pragma unroll
            for (int nt = 0; nt < 4; nt++)
                env[nt] = *(const float2*)&em[((size_t)b * LL + t + 1) * NN + jn[nt]];
            mkn = mask[b * LL + t + 1];
        }

        // ---- MMA: tot = P @ E ; even/odd k chains, depth 4 each ----
        float accE[4][4], accO[4][4];
#pragma unroll
        for (int nt = 0; nt < 4; nt++)
#pragma unroll
            for (int i = 0; i < 4; i++) { accE[nt][i] = 0.f; accO[nt][i] = 0.f; }
        {
            uint32_t abase = psb + (uint32_t)pr * BUFB
                           + (lane & 15) * ROWB + (lane >> 4) * 16;
#pragma unroll
            for (int kk = 0; kk < 8; kk += 2) {
                uint32_t a0, a1, a2, a3;
                ldm4(a0, a1, a2, a3, abase + kk * 32);
#pragma unroll
                for (int nt = 0; nt < 4; nt++)
                    mma16816(accE[nt], a0, a1, a2, a3, Bf0[nt][kk], Bf1[nt][kk]);
                uint32_t d0, d1, d2, d3;
                ldm4(d0, d1, d2, d3, abase + (kk + 1) * 32);
#pragma unroll
                for (int nt = 0; nt < 4; nt++)
                    mma16816(accO[nt], d0, d1, d2, d3, Bf0[nt][kk + 1], Bf1[nt][kk + 1]);
            }
        }

        // ---- epilogue ----
        float2 qc[4];
#pragma unroll
        for (int nt = 0; nt < 4; nt++) {
            qc[nt].x = (accE[nt][0] + accO[nt][0]) * sc[nt].x;
            qc[nt].y = (accE[nt][1] + accO[nt][1]) * sc[nt].y;
        }
        if (mk == 1.0f) {
#pragma unroll
            for (int nt = 0; nt < 4; nt++) qv[nt] = qc[nt];
        } else if (mk == 0.0f) {
#pragma unroll
            for (int nt = 0; nt < 4; nt++) { qv[nt].x *= inv; qv[nt].y *= inv; }
        } else {
#pragma unroll
            for (int nt = 0; nt < 4; nt++) {
                qv[nt].x = __expf(mk * __logf(qc[nt].x) + (1.f - mk) * __logf(qv[nt].x * inv));
                qv[nt].y = __expf(mk * __logf(qc[nt].y) + (1.f - mk) * __logf(qv[nt].y * inv));
            }
        }

        if (writer) {
            Lr -= __logf(inv);              // L += log(q_{t-1}[0])
            rinv[g][pw][r] = frcp(qv[0].x);
        }
        if (real) {
#pragma unroll
            for (int nt = 0; nt < 4; nt++)
                *(uint32_t*)((char*)psh[g] + (uint32_t)pw * BUFB + r * ROWB + jn[nt] * 2)
                    = bfpack(qv[nt].x, qv[nt].y);
        }
        emv[0] = env[0]; emv[1] = env[1]; emv[2] = env[2]; emv[3] = env[3];
        mk = mkn;
        gbar(g);
    }

    // ---- final: normalizer[b] = L[b] + log(sum_j q[b][j]) ----
    if (real) {
#pragma unroll
        for (int nt = 0; nt < 4; nt++) {
            sred[g][r][jn[nt]]     = qv[nt].x;
            sred[g][r][jn[nt] + 1] = qv[nt].y;
        }
        if (writer) Lsh[g][r] = Lr;
    }
    gbar(g);
    if (w < GRB) {
        float s = sred[g][w][lane] + sred[g][w][lane + 32] +
                  sred[g][w][lane + 64] + sred[g][w][lane + 96];
#pragma unroll
        for (int o = 16; o; o >>= 1)
            s += __shfl_xor_sync(0xffffffffu, s, o);
        if (lane == 0) g_norm[b0 + w] = Lsh[g][w] + __logf(s);
    }
}

// ---------------------------------------------------------------------------
// Path score. One block (128 threads) per batch.
// ---------------------------------------------------------------------------
__global__ __launch_bounds__(128)
void crf_path(const float* __restrict__ em,
              const int*   __restrict__ tgt,
              const float* __restrict__ mask,
              const float* __restrict__ start,
              const float* __restrict__ trans) {
    const int bb = blockIdx.x;
    const int tid = threadIdx.x;
    __shared__ float red[128];

    const size_t embase = (size_t)bb * LL * NN;
    float s = 0.0f;
    for (int t = tid; t < LL; t += 128) {
        if (t == 0) {
            int t0 = tgt[bb * LL];
            s += start[t0] + em[embase + t0];
        } else {
            int prev = tgt[bb * LL + t - 1];
            int cur  = tgt[bb * LL + t];
            s += mask[bb * LL + t] *
                 (trans[prev * NN + cur] + em[embase + (size_t)t * NN + cur]);
        }
    }
    red[tid] = s;
    __syncthreads();
#pragma unroll
    for (int o = 64; o; o >>= 1) {
        if (tid < o) red[tid] += red[tid + o];
        __syncthreads();
    }
    if (tid == 0) g_path[bb] = red[0];
}

// ---------------------------------------------------------------------------
// mean(normalizer - path)
// ---------------------------------------------------------------------------
__global__ __launch_bounds__(512)
void crf_final(float* __restrict__ out) {
    const int tid = threadIdx.x;
    __shared__ float wsum[16];
    float v = g_norm[tid] - g_path[tid];
#pragma unroll
    for (int o = 16; o; o >>= 1) v += __shfl_xor_sync(0xffffffffu, v, o);
    if ((tid & 31) == 0) wsum[tid >> 5] = v;
    __syncthreads();
    if (tid < 32) {
        float x = (tid < 16) ? wsum[tid] : 0.0f;
#pragma unroll
        for (int o = 8; o; o >>= 1) x += __shfl_xor_sync(0xffffffffu, x, o);
        if (tid == 0) out[0] = x * (1.0f / (float)BB);
    }
}

// ---------------------------------------------------------------------------
// Launch
// ---------------------------------------------------------------------------
extern "C" void kernel_launch(void* const* d_in, const int* in_sizes, int n_in,
                              void* d_out, int out_size) {
    const float* emission    = (const float*)d_in[0];
    const int*   target      = (const int*)  d_in[1];
    const float* mask        = (const float*)d_in[2];
    const float* start_trans = (const float*)d_in[3];
    const float* trans       = (const float*)d_in[4];
    float* out = (float*)d_out;

    crf_forward<<<BB / (NGRP * GRB), 256>>>(emission, mask, start_trans, trans);
    crf_path<<<BB, 128>>>(emission, target, mask, start_trans, trans);
    crf_final<<<1, 512>>>(out);
}